// round 6
// baseline (speedup 1.0000x reference)
#include <cuda_runtime.h>
#include <cstdint>

#define MAXQ 4096
#define TPB 256
#define MAXIT 8   // supports N up to TPB*MAXIT = 2048

// Packed per-query params
static __device__ float4 g_px[MAXQ];   // (c0, c1, c2, Ix as float bits) for x-stage
static __device__ int    g_Iy[MAXQ];
static __device__ float4 g_dy[MAXQ];   // (h0, h1, h2, h3*r) for y-stage

// Precompute: one block per (axis-kind, chunk). Axis staged in smem so the
// binary search hits smem (~30cyc/step) instead of L2 (~250cyc/step).
__global__ void precompute_kernel(const float* __restrict__ xaxis,
                                  const float* __restrict__ yaxis,
                                  const float* __restrict__ xs,
                                  const float* __restrict__ ys,
                                  int N) {
    extern __shared__ float ax[];
    bool is_y = (blockIdx.y != 0);
    const float* axis = is_y ? yaxis : xaxis;
    const float* qs   = is_y ? ys    : xs;
    for (int i = threadIdx.x; i < N; i += blockDim.x)
        ax[i] = axis[i];
    __syncthreads();

    int q = blockIdx.x * blockDim.x + threadIdx.x;
    if (q >= N) return;
    float v = qs[q];
    // Exact replica of jnp.searchsorted(axis[1:-1], v, side='left')
    int lo = 0, hi = N - 2;
    while (lo < hi) {
        int mid = (lo + hi) >> 1;
        if (ax[1 + mid] < v) lo = mid + 1; else hi = mid;
    }
    int I = lo;
    float x0 = ax[I], x1 = ax[I + 1], x2 = ax[I + 2];
    float dx = x1 - x0;
    float t = (v - x0) / dx;
    float t2 = t * t, t3 = t2 * t;
    float h0 = 1.0f - 3.0f * t2 + 2.0f * t3;
    float h1 = t - 2.0f * t2 + t3;
    float h2 = 3.0f * t2 - 2.0f * t3;
    float h3 = t3 - t2;
    float r = dx / (x2 - x1);
    if (!is_y) {
        // fold Hermite basis + slope terms into a 3-tap stencil
        g_px[q] = make_float4(h0 - h1, h1 + h2 - h3 * r, h3 * r, __int_as_float(I));
    } else {
        g_Iy[q] = I;
        g_dy[q] = make_float4(h0, h1, h2, h3 * r);
    }
}

// Fully fused, one block per output row (b, qy).
// out[qx] = c0*w[Ix] + c1*w[Ix+1] + c2*w[Ix+2]
//         + d1*(v1-v0) + d3*(s2-v1)
// where w[i] = d0*S[Iy][i] + d2*S[Iy+1][i] is precombined in the fill
// (d uniform per block), halving the randomly-gathered smem bytes.
__global__ __launch_bounds__(TPB) void fused_kernel(const float* __restrict__ signal,
                                                    float* __restrict__ out,
                                                    int N) {
    extern __shared__ float w[];       // N floats: d0*S[Iy][i] + d2*S[Iy+1][i]
    int b  = blockIdx.x / N;
    int qy = blockIdx.x - b * N;
    int Iy = g_Iy[qy];
    float4 d = g_dy[qy];
    size_t plane = (size_t)b * N * N;
    const float* __restrict__ r0 = signal + plane + (size_t)Iy * N;
    const float* __restrict__ r1 = r0 + N;
    const float* __restrict__ r2 = r1 + N;
    float* __restrict__ orow = out + plane + (size_t)qy * N;

    int iters = N / TPB;                // 4 for N=1024
    float v0[MAXIT], v1[MAXIT];

#pragma unroll
    for (int it = 0; it < MAXIT; ++it) {
        if (it >= iters) break;
        int q = threadIdx.x + it * TPB;
        float a  = __ldg(r0 + q);
        float bb = __ldg(r1 + q);
        v0[it] = a; v1[it] = bb;
        w[q] = d.x * a + d.z * bb;
    }
    __syncthreads();

#pragma unroll
    for (int it = 0; it < MAXIT; ++it) {
        if (it >= iters) break;
        int q = threadIdx.x + it * TPB;
        float4 p = g_px[q];
        int I = __float_as_int(p.w);
        float g = p.x * w[I] + p.y * w[I + 1] + p.z * w[I + 2];
        float s2 = __ldg(r2 + q);
        orow[q] = g + d.y * (v1[it] - v0[it]) + d.w * (s2 - v1[it]);
    }
}

extern "C" void kernel_launch(void* const* d_in, const int* in_sizes, int n_in,
                              void* d_out, int out_size) {
    const float* xaxis  = (const float*)d_in[0];
    const float* yaxis  = (const float*)d_in[1];
    const float* signal = (const float*)d_in[2];
    const float* xs     = (const float*)d_in[3];
    const float* ys     = (const float*)d_in[4];
    float* out = (float*)d_out;

    int N = in_sizes[0];                       // 1024
    int B = (int)((long long)in_sizes[2] / ((long long)N * N));  // 32

    dim3 pg((N + TPB - 1) / TPB, 2);
    precompute_kernel<<<pg, TPB, N * sizeof(float)>>>(xaxis, yaxis, xs, ys, N);
    fused_kernel<<<B * N, TPB, N * sizeof(float)>>>(signal, out, N);
}

// round 7
// speedup vs baseline: 2.1604x; 2.1604x over previous
#include <cuda_runtime.h>
#include <cstdint>

#define MAXQ 4096
#define TPB 256

// Packed per-query params
static __device__ float4 g_px[MAXQ];   // (c0, c1, c2, Ix as float bits) for x-stage
static __device__ int    g_Iy[MAXQ];
static __device__ float4 g_dy[MAXQ];   // (h0, h1, h2, h3*r) for y-stage

// Precompute: axis staged in smem so the binary search hits smem.
__global__ void precompute_kernel(const float* __restrict__ xaxis,
                                  const float* __restrict__ yaxis,
                                  const float* __restrict__ xs,
                                  const float* __restrict__ ys,
                                  int N) {
    extern __shared__ float ax[];
    bool is_y = (blockIdx.y != 0);
    const float* axis = is_y ? yaxis : xaxis;
    const float* qs   = is_y ? ys    : xs;
    for (int i = threadIdx.x; i < N; i += blockDim.x)
        ax[i] = axis[i];
    __syncthreads();

    int q = blockIdx.x * blockDim.x + threadIdx.x;
    if (q >= N) return;
    float v = qs[q];
    // Exact replica of jnp.searchsorted(axis[1:-1], v, side='left')
    int lo = 0, hi = N - 2;
    while (lo < hi) {
        int mid = (lo + hi) >> 1;
        if (ax[1 + mid] < v) lo = mid + 1; else hi = mid;
    }
    int I = lo;
    float x0 = ax[I], x1 = ax[I + 1], x2 = ax[I + 2];
    float dx = x1 - x0;
    float t = (v - x0) / dx;
    float t2 = t * t, t3 = t2 * t;
    float h0 = 1.0f - 3.0f * t2 + 2.0f * t3;
    float h1 = t - 2.0f * t2 + t3;
    float h2 = 3.0f * t2 - 2.0f * t3;
    float h3 = t3 - t2;
    float r = dx / (x2 - x1);
    if (!is_y) {
        g_px[q] = make_float4(h0 - h1, h1 + h2 - h3 * r, h3 * r, __int_as_float(I));
    } else {
        g_Iy[q] = I;
        g_dy[q] = make_float4(h0, h1, h2, h3 * r);
    }
}

// Fully fused, one block per output row (b, qy).
// out[qx] = c0*w[Ix] + c1*w[Ix+1] + c2*w[Ix+2] + colt + d3*s2
// with w[i]  = d0*S[Iy][i] + d2*S[Iy+1][i]            (precombined gather array)
//      colt  = d1*(S[Iy+1][qx]-S[Iy][qx]) - d3*S[Iy+1][qx]  (1 reg across sync)
// __launch_bounds__(TPB, 8) pins regs at 32 -> 8 blocks/SM.
template <int ITERS>
__global__ __launch_bounds__(TPB, 8) void fused_kernel(const float* __restrict__ signal,
                                                       float* __restrict__ out,
                                                       int N) {
    extern __shared__ float w[];       // N floats
    int b  = blockIdx.x / N;
    int qy = blockIdx.x - b * N;
    int Iy = g_Iy[qy];
    float4 d = g_dy[qy];
    size_t plane = (size_t)b * N * N;
    const float* __restrict__ r0 = signal + plane + (size_t)Iy * N;
    const float* __restrict__ r1 = r0 + N;
    const float* __restrict__ r2 = r1 + N;
    float* __restrict__ orow = out + plane + (size_t)qy * N;

    float colt[ITERS];

#pragma unroll
    for (int it = 0; it < ITERS; ++it) {
        int q = threadIdx.x + it * TPB;
        float a  = __ldg(r0 + q);
        float bb = __ldg(r1 + q);
        colt[it] = d.y * (bb - a) - d.w * bb;
        w[q] = d.x * a + d.z * bb;
    }
    __syncthreads();

#pragma unroll
    for (int it = 0; it < ITERS; ++it) {
        int q = threadIdx.x + it * TPB;
        float4 p = g_px[q];
        int I = __float_as_int(p.w);
        float g = p.x * w[I] + p.y * w[I + 1] + p.z * w[I + 2];
        float s2 = __ldg(r2 + q);
        orow[q] = g + colt[it] + d.w * s2;
    }
}

// Generic fallback for N not a multiple of TPB*known-iters
__global__ __launch_bounds__(TPB) void fused_kernel_gen(const float* __restrict__ signal,
                                                        float* __restrict__ out,
                                                        int N) {
    extern __shared__ float w[];
    int b  = blockIdx.x / N;
    int qy = blockIdx.x - b * N;
    int Iy = g_Iy[qy];
    float4 d = g_dy[qy];
    size_t plane = (size_t)b * N * N;
    const float* __restrict__ r0 = signal + plane + (size_t)Iy * N;
    const float* __restrict__ r1 = r0 + N;
    const float* __restrict__ r2 = r1 + N;
    float* __restrict__ orow = out + plane + (size_t)qy * N;

    for (int q = threadIdx.x; q < N; q += TPB)
        w[q] = d.x * __ldg(r0 + q) + d.z * __ldg(r1 + q);
    __syncthreads();
    for (int q = threadIdx.x; q < N; q += TPB) {
        float4 p = g_px[q];
        int I = __float_as_int(p.w);
        float g = p.x * w[I] + p.y * w[I + 1] + p.z * w[I + 2];
        float a = __ldg(r0 + q), bb = __ldg(r1 + q), s2 = __ldg(r2 + q);
        orow[q] = g + d.y * (bb - a) + d.w * (s2 - bb);
    }
}

extern "C" void kernel_launch(void* const* d_in, const int* in_sizes, int n_in,
                              void* d_out, int out_size) {
    const float* xaxis  = (const float*)d_in[0];
    const float* yaxis  = (const float*)d_in[1];
    const float* signal = (const float*)d_in[2];
    const float* xs     = (const float*)d_in[3];
    const float* ys     = (const float*)d_in[4];
    float* out = (float*)d_out;

    int N = in_sizes[0];                       // 1024
    int B = (int)((long long)in_sizes[2] / ((long long)N * N));  // 32

    dim3 pg((N + TPB - 1) / TPB, 2);
    precompute_kernel<<<pg, TPB, N * sizeof(float)>>>(xaxis, yaxis, xs, ys, N);
    if (N == 1024)
        fused_kernel<4><<<B * N, TPB, N * sizeof(float)>>>(signal, out, N);
    else if (N == 2048)
        fused_kernel<8><<<B * N, TPB, N * sizeof(float)>>>(signal, out, N);
    else if (N == 512)
        fused_kernel<2><<<B * N, TPB, N * sizeof(float)>>>(signal, out, N);
    else
        fused_kernel_gen<<<B * N, TPB, N * sizeof(float)>>>(signal, out, N);
}

// round 8
// speedup vs baseline: 2.3612x; 1.0929x over previous
#include <cuda_runtime.h>
#include <cstdint>

#define MAXQ 4096
#define TPB 256
#define TPB2 512

// Packed per-query params
static __device__ float4 g_px[MAXQ];   // (c0, c1, c2, Ix as float bits) for x-stage
static __device__ int    g_Iy[MAXQ];
static __device__ float4 g_dy[MAXQ];   // (h0, h1, h2, h3*r) for y-stage

// Precompute: axis staged in smem so the binary search hits smem.
__global__ void precompute_kernel(const float* __restrict__ xaxis,
                                  const float* __restrict__ yaxis,
                                  const float* __restrict__ xs,
                                  const float* __restrict__ ys,
                                  int N) {
    extern __shared__ float ax[];
    bool is_y = (blockIdx.y != 0);
    const float* axis = is_y ? yaxis : xaxis;
    const float* qs   = is_y ? ys    : xs;
    for (int i = threadIdx.x; i < N; i += blockDim.x)
        ax[i] = axis[i];
    __syncthreads();

    int q = blockIdx.x * blockDim.x + threadIdx.x;
    if (q >= N) return;
    float v = qs[q];
    // Exact replica of jnp.searchsorted(axis[1:-1], v, side='left')
    int lo = 0, hi = N - 2;
    while (lo < hi) {
        int mid = (lo + hi) >> 1;
        if (ax[1 + mid] < v) lo = mid + 1; else hi = mid;
    }
    int I = lo;
    float x0 = ax[I], x1 = ax[I + 1], x2 = ax[I + 2];
    float dx = x1 - x0;
    float t = (v - x0) / dx;
    float t2 = t * t, t3 = t2 * t;
    float h0 = 1.0f - 3.0f * t2 + 2.0f * t3;
    float h1 = t - 2.0f * t2 + t3;
    float h2 = 3.0f * t2 - 2.0f * t3;
    float h3 = t3 - t2;
    float r = dx / (x2 - x1);
    if (!is_y) {
        g_px[q] = make_float4(h0 - h1, h1 + h2 - h3 * r, h3 * r, __int_as_float(I));
    } else {
        g_Iy[q] = I;
        g_dy[q] = make_float4(h0, h1, h2, h3 * r);
    }
}

// Batch-paired fused kernel: one block per (batch-pair, qy) output row.
// Both batches share identical gather indices/coefficients (they depend only
// on qx/qy), so w is float2 = (w for batch b0, w for batch b0+1) and each
// random LDS.64 gather serves two outputs. g_px is read once per pair.
template <int ITERS>
__global__ __launch_bounds__(TPB2, 4) void fused2_kernel(const float* __restrict__ signal,
                                                         float* __restrict__ out,
                                                         int N) {
    extern __shared__ float2 w2[];     // N entries
    int bp = blockIdx.x / N;
    int qy = blockIdx.x - bp * N;
    int Iy = g_Iy[qy];
    float4 d = g_dy[qy];
    size_t pstride = (size_t)N * N;
    size_t plane0 = (size_t)(bp * 2) * pstride;
    const float* __restrict__ ra = signal + plane0 + (size_t)Iy * N;        // batch b0
    const float* __restrict__ rb = ra + pstride;                            // batch b0+1
    float* __restrict__ oa = out + plane0 + (size_t)qy * N;
    float* __restrict__ ob = oa + pstride;

    float colt0[ITERS], colt1[ITERS];

#pragma unroll
    for (int it = 0; it < ITERS; ++it) {
        int q = threadIdx.x + it * TPB2;
        float a0 = __ldg(ra + q);
        float b0 = __ldg(ra + N + q);
        float a1 = __ldg(rb + q);
        float b1 = __ldg(rb + N + q);
        colt0[it] = d.y * (b0 - a0) - d.w * b0;
        colt1[it] = d.y * (b1 - a1) - d.w * b1;
        w2[q] = make_float2(d.x * a0 + d.z * b0, d.x * a1 + d.z * b1);
    }
    __syncthreads();

#pragma unroll
    for (int it = 0; it < ITERS; ++it) {
        int q = threadIdx.x + it * TPB2;
        float4 p = g_px[q];
        int I = __float_as_int(p.w);
        float2 wa = w2[I];
        float2 wb = w2[I + 1];
        float2 wc = w2[I + 2];
        float g0 = p.x * wa.x + p.y * wb.x + p.z * wc.x;
        float g1 = p.x * wa.y + p.y * wb.y + p.z * wc.y;
        float s20 = __ldg(ra + 2 * N + q);
        float s21 = __ldg(rb + 2 * N + q);
        oa[q] = g0 + colt0[it] + d.w * s20;
        ob[q] = g1 + colt1[it] + d.w * s21;
    }
}

// Single-batch kernel (fallback for odd B), proven at R7.
template <int ITERS>
__global__ __launch_bounds__(TPB, 8) void fused_kernel(const float* __restrict__ signal,
                                                       float* __restrict__ out,
                                                       int N) {
    extern __shared__ float w[];
    int b  = blockIdx.x / N;
    int qy = blockIdx.x - b * N;
    int Iy = g_Iy[qy];
    float4 d = g_dy[qy];
    size_t plane = (size_t)b * N * N;
    const float* __restrict__ r0 = signal + plane + (size_t)Iy * N;
    const float* __restrict__ r1 = r0 + N;
    const float* __restrict__ r2 = r1 + N;
    float* __restrict__ orow = out + plane + (size_t)qy * N;

    float colt[ITERS];
#pragma unroll
    for (int it = 0; it < ITERS; ++it) {
        int q = threadIdx.x + it * TPB;
        float a  = __ldg(r0 + q);
        float bb = __ldg(r1 + q);
        colt[it] = d.y * (bb - a) - d.w * bb;
        w[q] = d.x * a + d.z * bb;
    }
    __syncthreads();
#pragma unroll
    for (int it = 0; it < ITERS; ++it) {
        int q = threadIdx.x + it * TPB;
        float4 p = g_px[q];
        int I = __float_as_int(p.w);
        float g = p.x * w[I] + p.y * w[I + 1] + p.z * w[I + 2];
        float s2 = __ldg(r2 + q);
        orow[q] = g + colt[it] + d.w * s2;
    }
}

// Generic fallback
__global__ __launch_bounds__(TPB) void fused_kernel_gen(const float* __restrict__ signal,
                                                        float* __restrict__ out,
                                                        int N) {
    extern __shared__ float w[];
    int b  = blockIdx.x / N;
    int qy = blockIdx.x - b * N;
    int Iy = g_Iy[qy];
    float4 d = g_dy[qy];
    size_t plane = (size_t)b * N * N;
    const float* __restrict__ r0 = signal + plane + (size_t)Iy * N;
    const float* __restrict__ r1 = r0 + N;
    const float* __restrict__ r2 = r1 + N;
    float* __restrict__ orow = out + plane + (size_t)qy * N;

    for (int q = threadIdx.x; q < N; q += TPB)
        w[q] = d.x * __ldg(r0 + q) + d.z * __ldg(r1 + q);
    __syncthreads();
    for (int q = threadIdx.x; q < N; q += TPB) {
        float4 p = g_px[q];
        int I = __float_as_int(p.w);
        float g = p.x * w[I] + p.y * w[I + 1] + p.z * w[I + 2];
        float a = __ldg(r0 + q), bb = __ldg(r1 + q), s2 = __ldg(r2 + q);
        orow[q] = g + d.y * (bb - a) + d.w * (s2 - bb);
    }
}

extern "C" void kernel_launch(void* const* d_in, const int* in_sizes, int n_in,
                              void* d_out, int out_size) {
    const float* xaxis  = (const float*)d_in[0];
    const float* yaxis  = (const float*)d_in[1];
    const float* signal = (const float*)d_in[2];
    const float* xs     = (const float*)d_in[3];
    const float* ys     = (const float*)d_in[4];
    float* out = (float*)d_out;

    int N = in_sizes[0];                       // 1024
    int B = (int)((long long)in_sizes[2] / ((long long)N * N));  // 32

    dim3 pg((N + TPB - 1) / TPB, 2);
    precompute_kernel<<<pg, TPB, N * sizeof(float)>>>(xaxis, yaxis, xs, ys, N);

    if ((B % 2) == 0 && N == 1024) {
        fused2_kernel<2><<<(B / 2) * N, TPB2, N * sizeof(float2)>>>(signal, out, N);
    } else if ((B % 2) == 0 && N == 2048) {
        fused2_kernel<4><<<(B / 2) * N, TPB2, N * sizeof(float2)>>>(signal, out, N);
    } else if ((B % 2) == 0 && N == 512) {
        fused2_kernel<1><<<(B / 2) * N, TPB2, N * sizeof(float2)>>>(signal, out, N);
    } else if (N == 1024) {
        fused_kernel<4><<<B * N, TPB, N * sizeof(float)>>>(signal, out, N);
    } else {
        fused_kernel_gen<<<B * N, TPB, N * sizeof(float)>>>(signal, out, N);
    }
}

// round 9
// speedup vs baseline: 2.6107x; 1.1057x over previous
#include <cuda_runtime.h>
#include <cstdint>

#define MAXQ 4096
#define TPB 256
#define TPB2 512

// Packed per-query params
static __device__ float4 g_px[MAXQ];   // (c0, c1, c2, Ix as float bits) for x-stage
static __device__ int    g_Iy[MAXQ];
static __device__ float4 g_dy[MAXQ];   // (h0, h1, h2, h3*r) for y-stage

// Precompute: axis staged in smem so the binary search hits smem.
__global__ void precompute_kernel(const float* __restrict__ xaxis,
                                  const float* __restrict__ yaxis,
                                  const float* __restrict__ xs,
                                  const float* __restrict__ ys,
                                  int N) {
    extern __shared__ float ax[];
    bool is_y = (blockIdx.y != 0);
    const float* axis = is_y ? yaxis : xaxis;
    const float* qs   = is_y ? ys    : xs;
    for (int i = threadIdx.x; i < N; i += blockDim.x)
        ax[i] = axis[i];
    __syncthreads();

    int q = blockIdx.x * blockDim.x + threadIdx.x;
    if (q >= N) return;
    float v = qs[q];
    // Exact replica of jnp.searchsorted(axis[1:-1], v, side='left')
    int lo = 0, hi = N - 2;
    while (lo < hi) {
        int mid = (lo + hi) >> 1;
        if (ax[1 + mid] < v) lo = mid + 1; else hi = mid;
    }
    int I = lo;
    float x0 = ax[I], x1 = ax[I + 1], x2 = ax[I + 2];
    float dx = x1 - x0;
    float t = (v - x0) / dx;
    float t2 = t * t, t3 = t2 * t;
    float h0 = 1.0f - 3.0f * t2 + 2.0f * t3;
    float h1 = t - 2.0f * t2 + t3;
    float h2 = 3.0f * t2 - 2.0f * t3;
    float h3 = t3 - t2;
    float r = dx / (x2 - x1);
    if (!is_y) {
        g_px[q] = make_float4(h0 - h1, h1 + h2 - h3 * r, h3 * r, __int_as_float(I));
    } else {
        g_Iy[q] = I;
        g_dy[q] = make_float4(h0, h1, h2, h3 * r);
    }
}

// 4-batch fused kernel: one block per (batch-quad, qy) output row.
// All 4 batch planes share the same gather indices/coefficients, so w is
// float4 and each random LDS.128 gather serves FOUR outputs.
template <int ITERS>
__global__ __launch_bounds__(TPB2, 4) void fused4_kernel(const float* __restrict__ signal,
                                                         float* __restrict__ out,
                                                         int N) {
    extern __shared__ float4 w4[];     // N entries, 16B-aligned -> LDS.128 ok
    int bq = blockIdx.x / N;
    int qy = blockIdx.x - bq * N;
    int Iy = g_Iy[qy];
    float4 d = g_dy[qy];
    size_t pstride = (size_t)N * N;
    const float* __restrict__ rbase = signal + (size_t)(bq * 4) * pstride + (size_t)Iy * N;
    float* __restrict__ obase = out + (size_t)(bq * 4) * pstride + (size_t)qy * N;

    float colt[ITERS][4];

#pragma unroll
    for (int it = 0; it < ITERS; ++it) {
        int q = threadIdx.x + it * TPB2;
        float wv[4];
#pragma unroll
        for (int k = 0; k < 4; ++k) {
            float a = __ldg(rbase + (size_t)k * pstride + q);
            float b = __ldg(rbase + (size_t)k * pstride + N + q);
            colt[it][k] = d.y * (b - a) - d.w * b;
            wv[k] = d.x * a + d.z * b;
        }
        w4[q] = make_float4(wv[0], wv[1], wv[2], wv[3]);
    }
    __syncthreads();

#pragma unroll
    for (int it = 0; it < ITERS; ++it) {
        int q = threadIdx.x + it * TPB2;
        float4 p = g_px[q];
        int I = __float_as_int(p.w);
        float4 wa = w4[I];
        float4 wb = w4[I + 1];
        float4 wc = w4[I + 2];
#pragma unroll
        for (int k = 0; k < 4; ++k) {
            float ga = (k == 0) ? wa.x : (k == 1) ? wa.y : (k == 2) ? wa.z : wa.w;
            float gb = (k == 0) ? wb.x : (k == 1) ? wb.y : (k == 2) ? wb.z : wb.w;
            float gc = (k == 0) ? wc.x : (k == 1) ? wc.y : (k == 2) ? wc.z : wc.w;
            float g = p.x * ga + p.y * gb + p.z * gc;
            float s2 = __ldg(rbase + (size_t)k * pstride + 2 * N + q);
            obase[(size_t)k * pstride + q] = g + colt[it][k] + d.w * s2;
        }
    }
}

// 2-batch fused kernel (proven 78.8us at R8) — fallback.
template <int ITERS>
__global__ __launch_bounds__(TPB2, 4) void fused2_kernel(const float* __restrict__ signal,
                                                         float* __restrict__ out,
                                                         int N) {
    extern __shared__ float2 w2[];     // N entries
    int bp = blockIdx.x / N;
    int qy = blockIdx.x - bp * N;
    int Iy = g_Iy[qy];
    float4 d = g_dy[qy];
    size_t pstride = (size_t)N * N;
    size_t plane0 = (size_t)(bp * 2) * pstride;
    const float* __restrict__ ra = signal + plane0 + (size_t)Iy * N;
    const float* __restrict__ rb = ra + pstride;
    float* __restrict__ oa = out + plane0 + (size_t)qy * N;
    float* __restrict__ ob = oa + pstride;

    float colt0[ITERS], colt1[ITERS];
#pragma unroll
    for (int it = 0; it < ITERS; ++it) {
        int q = threadIdx.x + it * TPB2;
        float a0 = __ldg(ra + q);
        float b0 = __ldg(ra + N + q);
        float a1 = __ldg(rb + q);
        float b1 = __ldg(rb + N + q);
        colt0[it] = d.y * (b0 - a0) - d.w * b0;
        colt1[it] = d.y * (b1 - a1) - d.w * b1;
        w2[q] = make_float2(d.x * a0 + d.z * b0, d.x * a1 + d.z * b1);
    }
    __syncthreads();
#pragma unroll
    for (int it = 0; it < ITERS; ++it) {
        int q = threadIdx.x + it * TPB2;
        float4 p = g_px[q];
        int I = __float_as_int(p.w);
        float2 wa = w2[I];
        float2 wb = w2[I + 1];
        float2 wc = w2[I + 2];
        float g0 = p.x * wa.x + p.y * wb.x + p.z * wc.x;
        float g1 = p.x * wa.y + p.y * wb.y + p.z * wc.y;
        float s20 = __ldg(ra + 2 * N + q);
        float s21 = __ldg(rb + 2 * N + q);
        oa[q] = g0 + colt0[it] + d.w * s20;
        ob[q] = g1 + colt1[it] + d.w * s21;
    }
}

// Generic single-batch fallback
__global__ __launch_bounds__(TPB) void fused_kernel_gen(const float* __restrict__ signal,
                                                        float* __restrict__ out,
                                                        int N) {
    extern __shared__ float w[];
    int b  = blockIdx.x / N;
    int qy = blockIdx.x - b * N;
    int Iy = g_Iy[qy];
    float4 d = g_dy[qy];
    size_t plane = (size_t)b * N * N;
    const float* __restrict__ r0 = signal + plane + (size_t)Iy * N;
    const float* __restrict__ r1 = r0 + N;
    const float* __restrict__ r2 = r1 + N;
    float* __restrict__ orow = out + plane + (size_t)qy * N;

    for (int q = threadIdx.x; q < N; q += TPB)
        w[q] = d.x * __ldg(r0 + q) + d.z * __ldg(r1 + q);
    __syncthreads();
    for (int q = threadIdx.x; q < N; q += TPB) {
        float4 p = g_px[q];
        int I = __float_as_int(p.w);
        float g = p.x * w[I] + p.y * w[I + 1] + p.z * w[I + 2];
        float a = __ldg(r0 + q), bb = __ldg(r1 + q), s2 = __ldg(r2 + q);
        orow[q] = g + d.y * (bb - a) + d.w * (s2 - bb);
    }
}

extern "C" void kernel_launch(void* const* d_in, const int* in_sizes, int n_in,
                              void* d_out, int out_size) {
    const float* xaxis  = (const float*)d_in[0];
    const float* yaxis  = (const float*)d_in[1];
    const float* signal = (const float*)d_in[2];
    const float* xs     = (const float*)d_in[3];
    const float* ys     = (const float*)d_in[4];
    float* out = (float*)d_out;

    int N = in_sizes[0];                       // 1024
    int B = (int)((long long)in_sizes[2] / ((long long)N * N));  // 32

    dim3 pg((N + TPB - 1) / TPB, 2);
    precompute_kernel<<<pg, TPB, N * sizeof(float)>>>(xaxis, yaxis, xs, ys, N);

    if ((B % 4) == 0 && N == 1024) {
        fused4_kernel<2><<<(B / 4) * N, TPB2, N * sizeof(float4)>>>(signal, out, N);
    } else if ((B % 4) == 0 && N == 2048) {
        fused4_kernel<4><<<(B / 4) * N, TPB2, N * sizeof(float4)>>>(signal, out, N);
    } else if ((B % 2) == 0 && N == 1024) {
        fused2_kernel<2><<<(B / 2) * N, TPB2, N * sizeof(float2)>>>(signal, out, N);
    } else {
        fused_kernel_gen<<<B * N, TPB, N * sizeof(float)>>>(signal, out, N);
    }
}